// round 13
// baseline (speedup 1.0000x reference)
#include <cuda_runtime.h>

namespace {

constexpr int T = 2048;
constexpr int B = 4096;
constexpr int BLK = 256;   // 32 chains/block; 128 blocks; 2 warps/SMSP on 128 SMs
constexpr int PF = 4;      // x prefetch depth

typedef unsigned long long u64;

// NOTE: all pure-math asm is NON-volatile so NVCC/ptxas may interleave the
// independent gate trees and hide latencies. (R12 and earlier had `volatile`
// on every wrapper, which pins program order between ALL asm statements and
// forced a near-serial schedule — the measured ~5 cyc/inst law.)
__device__ __forceinline__ u64 pack2(float lo, float hi) {
    u64 r; asm("mov.b64 %0,{%1,%2};" : "=l"(r) : "f"(lo), "f"(hi)); return r;
}
__device__ __forceinline__ void unpack2(u64 v, float& lo, float& hi) {
    asm("mov.b64 {%0,%1},%2;" : "=f"(lo), "=f"(hi) : "l"(v));
}
__device__ __forceinline__ u64 ffma2(u64 a, u64 b, u64 c) {
    u64 d; asm("fma.rn.f32x2 %0,%1,%2,%3;" : "=l"(d) : "l"(a), "l"(b), "l"(c)); return d;
}
__device__ __forceinline__ u64 fmul2(u64 a, u64 b) {
    u64 d; asm("mul.rn.f32x2 %0,%1,%2;" : "=l"(d) : "l"(a), "l"(b)); return d;
}
__device__ __forceinline__ u64 fadd2(u64 a, u64 b) {
    u64 d; asm("add.rn.f32x2 %0,%1,%2;" : "=l"(d) : "l"(a), "l"(b)); return d;
}
__device__ __forceinline__ float tanha(float x) {
    float y; asm("tanh.approx.f32 %0,%1;" : "=f"(y) : "f"(x)); return y;
}
__device__ __forceinline__ float hadd(u64 v) {
    float lo, hi; unpack2(v, lo, hi); return lo + hi;
}
__device__ __forceinline__ unsigned smem_u32(const void* p) {
    unsigned a;
    asm("{ .reg .u64 t; cvta.to.shared.u64 t, %1; cvt.u32.u64 %0, t; }" : "=r"(a) : "l"(p));
    return a;
}

// 8 threads per batch chain; lane l owns h_l and rows l (r), 8+l (z), 16+l (n).
// Exchange: STS.32 then two LDS.128 (same-warp LSU program order; these three
// REMAIN asm volatile so their mutual order is pinned). LDS.128 delivers h as
// ready-made f32x2 pairs. Gate rows in tree form, source-interleaved r/z/n.
// n-path: 0.5 pre-folded into Whn/bhn -> tree yields hnh = hn/2 directly;
// v = fma(thr, hnh, hnh + xn). sigma via MUFU.TANH with 1/2 pre-folded.
__global__ void __launch_bounds__(BLK, 1) gru_fused_kernel(
    const float* __restrict__ x,
    const float* __restrict__ W_ih,
    const float* __restrict__ W_hh,
    const float* __restrict__ b_ih,
    const float* __restrict__ b_hh,
    const float* __restrict__ W_fc,
    const float* __restrict__ b_fc,
    float* __restrict__ out)
{
    __shared__ float hx[BLK];              // 32 groups x 8 floats = 1KB

    const int l  = threadIdx.x & 7;        // lane within chain group
    const int gi = threadIdx.x >> 3;       // group within block
    const int b  = blockIdx.x * (BLK / 8) + gi;

    const unsigned sbase = smem_u32(hx) + gi * 32;   // group's 8-float slab
    const unsigned sme   = sbase + l * 4;            // my h slot

    const float HS = 0.5f;

    // ---- register-resident weights: rows l, 8+l, 16+l ----
    const int gr = l, gz = 8 + l, gn = 16 + l;
    u64 Whr[4], Whz[4], Whn[4];            // (W[g,2k], W[g,2k+1])
#pragma unroll
    for (int k = 0; k < 4; k++) {
        Whr[k] = pack2(HS * W_hh[gr * 8 + 2 * k], HS * W_hh[gr * 8 + 2 * k + 1]);
        Whz[k] = pack2(HS * W_hh[gz * 8 + 2 * k], HS * W_hh[gz * 8 + 2 * k + 1]);
        // 0.5 folded: the n tree yields hnh = 0.5*(Whn·h + b_hh)
        Whn[k] = pack2(HS * W_hh[gn * 8 + 2 * k], HS * W_hh[gn * 8 + 2 * k + 1]);
    }
    u64 Wxr[2], Wxz[2], Wxn[2];
#pragma unroll
    for (int k = 0; k < 2; k++) {
        Wxr[k] = pack2(HS * W_ih[gr * 4 + 2 * k], HS * W_ih[gr * 4 + 2 * k + 1]);
        Wxz[k] = pack2(HS * W_ih[gz * 4 + 2 * k], HS * W_ih[gz * 4 + 2 * k + 1]);
        Wxn[k] = pack2(W_ih[gn * 4 + 2 * k], W_ih[gn * 4 + 2 * k + 1]);
    }
    const u64 brp   = pack2(HS * (b_ih[gr] + b_hh[gr]), 0.0f);
    const u64 bzp   = pack2(HS * (b_ih[gz] + b_hh[gz]), 0.0f);
    const u64 bxnp  = pack2(b_ih[gn], 0.0f);
    const u64 bhn2p = pack2(HS * b_hh[gn], 0.0f);     // pre-halved n-bias

    const int o = l & 3;                   // fc output index (lanes 4-7 redundant)
    u64 Wf[4];
#pragma unroll
    for (int k = 0; k < 4; k++)
        Wf[k] = pack2(W_fc[o * 8 + 2 * k], W_fc[o * 8 + 2 * k + 1]);
    const u64 bfp = pack2(b_fc[o], 0.0f);

    const ulonglong2* xp = reinterpret_cast<const ulonglong2*>(x) + (size_t)b * T;
    float* op = out + (size_t)b * T * 4 + o;

    u64 H01 = 0, H23 = 0, H45 = 0, H67 = 0;   // h_{t-1} pairs
    float h = 0.0f;                            // my owned h_l

    // PF-deep x prefetch; loop unrolled by PF so shifts are register renaming
    ulonglong2 xb[PF];
#pragma unroll
    for (int i = 0; i < PF; i++) xb[i] = xp[i];

#pragma unroll 4
    for (int t = 0; t < T; t++) {
        const u64 xp0 = xb[0].x, xp1 = xb[0].y;
#pragma unroll
        for (int i = 0; i < PF - 1; i++) xb[i] = xb[i + 1];
        int tn = t + PF; tn = (tn < T) ? tn : (T - 1);
        xb[PF - 1] = xp[tn];

        // ---- x-side seeds (independent of h) ----
        u64 r1 = ffma2(Wxr[0], xp0, brp);
        u64 z1 = ffma2(Wxz[0], xp0, bzp);
        u64 xnp = ffma2(Wxn[0], xp0, bxnp);
        u64 r2 = fmul2(Wxr[1], xp1);
        u64 z2 = fmul2(Wxz[1], xp1);
        xnp = ffma2(Wxn[1], xp1, xnp);

        // ---- h-side trees, interleaved r/z/n for scheduling freedom ----
        r1 = ffma2(Whr[0], H01, r1);
        z1 = ffma2(Whz[0], H01, z1);
        u64 hn1 = ffma2(Whn[0], H01, bhn2p);
        r2 = ffma2(Whr[2], H45, r2);
        z2 = ffma2(Whz[2], H45, z2);
        u64 hn2 = fmul2(Whn[2], H45);
        r1 = ffma2(Whr[1], H23, r1);
        z1 = ffma2(Whz[1], H23, z1);
        hn1 = ffma2(Whn[1], H23, hn1);
        r2 = ffma2(Whr[3], H67, r2);
        z2 = ffma2(Whz[3], H67, z2);
        hn2 = ffma2(Whn[3], H67, hn2);

        // ---- activations ----
        const float thr = tanha(hadd(fadd2(r1, r2)));   // tanh(u_r/2)
        const float thz = tanha(hadd(fadd2(z1, z2)));   // tanh(u_z/2)

        const float hnh = hadd(fadd2(hn1, hn2));        // hn/2
        const float xn  = hadd(xnp);
        const float v   = fmaf(thr, hnh, hnh + xn);     // xn + r*hn
        const float n   = tanha(v);

        // h' = (1-z)n + z h ;  z = 0.5 + 0.5*thz
        const float omz = fmaf(-0.5f, thz, 0.5f);
        const float hh2 = 0.5f * h;                      // off-chain (old h)
        const float zh  = fmaf(thz, hh2, hh2);
        h = fmaf(omz, n, zh);

        // ---- exchange: volatile STS + LDS.128 pair loads (order pinned) ----
        asm volatile("st.shared.f32 [%0], %1;" :: "r"(sme), "f"(h) : "memory");
        asm volatile("ld.shared.v2.b64 {%0,%1}, [%2];"
                     : "=l"(H01), "=l"(H23) : "r"(sbase) : "memory");
        asm volatile("ld.shared.v2.b64 {%0,%1}, [%2];"
                     : "=l"(H45), "=l"(H67) : "r"(sbase + 16) : "memory");

        // ---- y_t from fresh pairs; lanes 0-3 store ----
        u64 ya = ffma2(Wf[0], H01, ffma2(Wf[1], H23, bfp));
        u64 yb = ffma2(Wf[2], H45, fmul2(Wf[3], H67));
        const float y = hadd(fadd2(ya, yb));
        if (l < 4) op[t * 4] = y;
    }
}

} // namespace

extern "C" void kernel_launch(void* const* d_in, const int* in_sizes, int n_in,
                              void* d_out, int out_size)
{
    const float* x    = (const float*)d_in[0];
    const float* W_ih = (const float*)d_in[1];
    const float* W_hh = (const float*)d_in[2];
    const float* b_ih = (const float*)d_in[3];
    const float* b_hh = (const float*)d_in[4];
    const float* W_fc = (const float*)d_in[5];
    const float* b_fc = (const float*)d_in[6];
    float* out = (float*)d_out;

    // 4096 chains x 8 lanes = 32768 threads; 128 blocks x 256 threads
    // -> 8 warps/SM on 128 SMs = 2 warps/SMSP.
    gru_fused_kernel<<<(B * 8) / BLK, BLK>>>(x, W_ih, W_hh, b_ih, b_hh, W_fc, b_fc, out);
}